// round 16
// baseline (speedup 1.0000x reference)
#include <cuda_runtime.h>
#include <cuda_fp16.h>

#define MAXN 100000
#define MAXE 1600000
#define HID 64
#define SCAN_BLK 1024
#define MAX_SCAN_BLOCKS 256

// ---- scratch (device globals; no allocation allowed) ----
// g_t16 holds t'[i] = (h @ W)[i] * dis[i]  (fp16)
__device__ __align__(256) __half g_t16[MAXN * HID];
__device__ __align__(256) __half g_agg16[MAXN * HID]; // relu(conv) output (fp16)
__device__ __align__(256) float g_dis[MAXN];          // deg^{-1/2}
__device__ __align__(256) int   g_deg[MAXN];          // zero at rest (self-restoring)
__device__ __align__(256) int   g_rowptr[MAXN + 1];
__device__ __align__(256) int   g_cursor[MAXN];
__device__ __align__(256) int   g_blocksum[MAX_SCAN_BLOCKS];
__device__ __align__(256) int   g_srcs[MAXE + 4];     // CSR: src node per slot

// ---------------- prep ----------------
// 4 edges per thread via int4 (E is a multiple of 4 in practice; tail handled).
__global__ void count_deg_kernel(const int* __restrict__ dst, int E) {
    int e = (blockIdx.x * blockDim.x + threadIdx.x) * 4;
    if (e + 4 <= E) {
        int4 d = *(const int4*)(dst + e);
        atomicAdd(&g_deg[d.x], 1);
        atomicAdd(&g_deg[d.y], 1);
        atomicAdd(&g_deg[d.z], 1);
        atomicAdd(&g_deg[d.w], 1);
    } else {
        for (; e < E; e++) atomicAdd(&g_deg[dst[e]], 1);
    }
}

// partial exclusive scan of g_deg; computes dis; zeroes g_deg after reading
// (keeps the at-rest state zero so count_deg needs no preceding memset).
__global__ void scan_part_kernel(int n) {
    __shared__ int sm[256];
    int tid = threadIdx.x;
    int base = blockIdx.x * SCAN_BLK + tid * 4;
    int v[4];
#pragma unroll
    for (int j = 0; j < 4; j++) {
        v[j] = (base + j < n) ? g_deg[base + j] : 0;
        if (base + j < n) {
            g_dis[base + j] = rsqrtf((float)(v[j] + 1));
            g_deg[base + j] = 0;
        }
    }
    int tsum = v[0] + v[1] + v[2] + v[3];
    sm[tid] = tsum;
    __syncthreads();
#pragma unroll
    for (int off = 1; off < 256; off <<= 1) {
        int t2 = (tid >= off) ? sm[tid - off] : 0;
        __syncthreads();
        sm[tid] += t2;
        __syncthreads();
    }
    if (tid == 255) g_blocksum[blockIdx.x] = sm[255];
    int run = sm[tid] - tsum;  // exclusive
#pragma unroll
    for (int j = 0; j < 4; j++) {
        if (base + j < n) g_rowptr[base + j] = run;
        run += v[j];
    }
}

// fused top-scan + fixup: every block redundantly prefix-sums the <=98
// block sums in smem, then applies its offsets. Also zeroes cursors.
__global__ void scan_fixup_kernel(int n, int E, int nsb) {
    __shared__ int off[128];
    int tid = threadIdx.x;
    if (tid < nsb) off[tid] = g_blocksum[tid];
    __syncthreads();
    if (tid == 0) {
        int run = 0;
        for (int i = 0; i < nsb; i++) { int t = off[i]; off[i] = run; run += t; }
    }
    __syncthreads();
    int i = blockIdx.x * blockDim.x + tid;
    if (i < n) {
        g_rowptr[i] += off[i / SCAN_BLK];
        g_cursor[i] = 0;
    } else if (i == n) {
        g_rowptr[n] = E;
    }
}

// 4 edges per thread via int4 reads.
__global__ void permute_kernel(const int* __restrict__ src,
                               const int* __restrict__ dst, int E) {
    int e = (blockIdx.x * blockDim.x + threadIdx.x) * 4;
    if (e + 4 <= E) {
        int4 s = *(const int4*)(src + e);
        int4 d = *(const int4*)(dst + e);
        int p0 = atomicAdd(&g_cursor[d.x], 1);
        g_srcs[g_rowptr[d.x] + p0] = s.x;
        int p1 = atomicAdd(&g_cursor[d.y], 1);
        g_srcs[g_rowptr[d.y] + p1] = s.y;
        int p2 = atomicAdd(&g_cursor[d.z], 1);
        g_srcs[g_rowptr[d.z] + p2] = s.z;
        int p3 = atomicAdd(&g_cursor[d.w], 1);
        g_srcs[g_rowptr[d.w] + p3] = s.w;
    } else {
        for (; e < E; e++) {
            int d = dst[e];
            int pos = atomicAdd(&g_cursor[d], 1);
            g_srcs[g_rowptr[d] + pos] = src[e];
        }
    }
}

// ---------------- tf32 tensor-core GEMM: t16[N,64] = (in[N,K] @ W) * dis ----
__device__ __forceinline__ unsigned int f2tf32(float f) {
    unsigned int u;
    asm("cvt.rna.tf32.f32 %0, %1;" : "=r"(u) : "f"(f));
    return u;
}

__device__ __forceinline__ float ld_elem(const float* p)  { return *p; }
__device__ __forceinline__ float ld_elem(const __half* p) { return __half2float(*p); }

__device__ __forceinline__ void mma_tf32(float* c,
                                         unsigned int a0, unsigned int a1,
                                         unsigned int a2, unsigned int a3,
                                         unsigned int b0, unsigned int b1) {
    asm volatile(
        "mma.sync.aligned.m16n8k8.row.col.f32.tf32.tf32.f32 "
        "{%0,%1,%2,%3}, {%4,%5,%6,%7}, {%8,%9}, {%0,%1,%2,%3};"
        : "+f"(c[0]), "+f"(c[1]), "+f"(c[2]), "+f"(c[3])
        : "r"(a0), "r"(a1), "r"(a2), "r"(a3), "r"(b0), "r"(b1));
}

// Block: 256 threads = 8 warps; tile = 128 nodes x 64 cols; warp = 16 nodes.
// A fragments loaded directly from gmem (fp32 for layer 1, fp16 after).
// W in smem, stride 72 (== 8 mod 32: B-frag banks conflict-free).
// Epilogue: scale row r by dis[r] before fp16 store (norm factorization).
// minBlocks=4 caps regs at 64 -> 32 warps/SM for latency hiding.
template <int K, typename T>
__global__ __launch_bounds__(256, 4) void gemm_tc_kernel(const T* __restrict__ in,
                                                         const float* __restrict__ W,
                                                         __half* __restrict__ out, int n) {
    constexpr int SW = 72;
    __shared__ unsigned int ws[K * SW];

    const int tid = threadIdx.x;
    const int base = blockIdx.x * 128;

    {
        const float4* W4 = (const float4*)W;
        for (int i = tid; i < K * 16; i += 256) {
            int row = i >> 4, c4 = i & 15;
            float4 v = W4[i];
            uint4 u = make_uint4(f2tf32(v.x), f2tf32(v.y), f2tf32(v.z), f2tf32(v.w));
            *(uint4*)(ws + row * SW + c4 * 4) = u;
        }
    }
    __syncthreads();

    const int wid  = tid >> 5;
    const int lane = tid & 31;
    const int g    = lane >> 2;
    const int tg   = lane & 3;

    int r0 = base + wid * 16 + g;
    int r1 = r0 + 8;
    bool p0 = r0 < n, p1 = r1 < n;
    const T* x0 = in + (size_t)(p0 ? r0 : 0) * K + tg;
    const T* x1 = in + (size_t)(p1 ? r1 : 0) * K + tg;

    float c[8][4];
#pragma unroll
    for (int nt = 0; nt < 8; nt++)
#pragma unroll
        for (int j = 0; j < 4; j++) c[nt][j] = 0.f;

#pragma unroll
    for (int ks = 0; ks < K / 8; ks++) {
        unsigned int a0 = f2tf32(p0 ? ld_elem(x0 + ks * 8)     : 0.f);
        unsigned int a2 = f2tf32(p0 ? ld_elem(x0 + ks * 8 + 4) : 0.f);
        unsigned int a1 = f2tf32(p1 ? ld_elem(x1 + ks * 8)     : 0.f);
        unsigned int a3 = f2tf32(p1 ? ld_elem(x1 + ks * 8 + 4) : 0.f);
        const unsigned int* bp = ws + (ks * 8 + tg) * SW + g;
#pragma unroll
        for (int nt = 0; nt < 8; nt++) {
            unsigned int b0 = bp[nt * 8];
            unsigned int b1 = bp[nt * 8 + 4 * SW];
            mma_tf32(c[nt], a0, a1, a2, a3, b0, b1);
        }
    }

    float d0 = p0 ? g_dis[r0] : 0.f;
    float d1 = p1 ? g_dis[r1] : 0.f;
#pragma unroll
    for (int nt = 0; nt < 8; nt++) {
        int col = nt * 8 + tg * 2;
        if (p0) {
            __half2 h = __floats2half2_rn(c[nt][0] * d0, c[nt][1] * d0);
            *(__half2*)(out + (size_t)r0 * 64 + col) = h;
        }
        if (p1) {
            __half2 h = __floats2half2_rn(c[nt][2] * d1, c[nt][3] * d1);
            *(__half2*)(out + (size_t)r1 * 64 + col) = h;
        }
    }
}

// ---------------- CSR gather (warp per node, 4B edges, fp16 out) -----------
// agg[d] = relu( dis[d] * (sum_e t'[src_e] + t'[d]) + b )
__global__ __launch_bounds__(256) void gather_kernel(const float* __restrict__ b,
                                                     int n) {
    int node = blockIdx.x * 8 + (threadIdx.x >> 5);  // 8 warps/block
    int l = threadIdx.x & 31;
    if (node >= n) return;

    const __half2* t2 = (const __half2*)g_t16;

    float2 acc = __half22float2(t2[node * 32 + l]);  // self-loop term t'[d]
    int e  = g_rowptr[node];
    int e1 = g_rowptr[node + 1];
    for (; e + 4 <= e1; e += 4) {
        int s0 = g_srcs[e];
        int s1 = g_srcs[e + 1];
        int s2 = g_srcs[e + 2];
        int s3 = g_srcs[e + 3];
        float2 f0 = __half22float2(t2[s0 * 32 + l]);
        float2 f1 = __half22float2(t2[s1 * 32 + l]);
        float2 f2 = __half22float2(t2[s2 * 32 + l]);
        float2 f3 = __half22float2(t2[s3 * 32 + l]);
        acc.x += f0.x + f1.x + f2.x + f3.x;
        acc.y += f0.y + f1.y + f2.y + f3.y;
    }
    for (; e < e1; e++) {
        float2 f0 = __half22float2(t2[g_srcs[e] * 32 + l]);
        acc.x += f0.x;
        acc.y += f0.y;
    }

    float dd = g_dis[node];
    float2 bb = ((const float2*)b)[l];
    float rx = fmaxf(fmaf(dd, acc.x, bb.x), 0.f);
    float ry = fmaxf(fmaf(dd, acc.y, bb.y), 0.f);
    ((__half2*)g_agg16)[node * 32 + l] = __floats2half2_rn(rx, ry);
}

// ---------------- pooling + output linear (MLP-4 node loop) ----------------
__global__ void pool_out_kernel(const int* __restrict__ batch,
                                const float* __restrict__ Wout,
                                const float* __restrict__ bout,
                                float* __restrict__ out,
                                float* __restrict__ pooled, int n) {
    int g = blockIdx.x;
    int c = threadIdx.x;  // 64 threads

    int a = 0, b = n;
    while (a < b) { int m = (a + b) >> 1; if (batch[m] < g) a = m + 1; else b = m; }
    int start = a;
    b = n;
    while (a < b) { int m = (a + b) >> 1; if (batch[m] <= g) a = m + 1; else b = m; }
    int end = a;

    float sum = 0.f, mx = 0.f;
    int i = start;
    for (; i + 4 <= end; i += 4) {
        float v0 = __half2float(g_agg16[(size_t)i * 64 + c]);
        float v1 = __half2float(g_agg16[(size_t)(i + 1) * 64 + c]);
        float v2 = __half2float(g_agg16[(size_t)(i + 2) * 64 + c]);
        float v3 = __half2float(g_agg16[(size_t)(i + 3) * 64 + c]);
        sum += (v0 + v1) + (v2 + v3);
        mx = fmaxf(fmaxf(mx, fmaxf(v0, v1)), fmaxf(v2, v3));
    }
    for (; i < end; i++) {
        float v = __half2float(g_agg16[(size_t)i * 64 + c]);
        sum += v;
        mx = fmaxf(mx, v);
    }
    int cnt = end - start;
    float mean = (cnt > 0) ? sum / (float)cnt : 0.f;

    pooled[(size_t)g * 128 + c] = mean;
    pooled[(size_t)g * 128 + 64 + c] = mx;

    float partial = mean * Wout[c] + mx * Wout[64 + c];
#pragma unroll
    for (int o = 16; o > 0; o >>= 1)
        partial += __shfl_down_sync(0xffffffffu, partial, o);
    __shared__ float ws[2];
    if ((threadIdx.x & 31) == 0) ws[threadIdx.x >> 5] = partial;
    __syncthreads();
    if (threadIdx.x == 0) out[g] = ws[0] + ws[1] + bout[0];
}

// ---------------- host ----------------
extern "C" void kernel_launch(void* const* d_in, const int* in_sizes, int n_in,
                              void* d_out, int out_size) {
    const float* x     = (const float*)d_in[0];
    const int*   edge  = (const int*)d_in[1];     // int64 inputs arrive as int32
    const int*   batch = (const int*)d_in[2];
    const float* W1 = (const float*)d_in[3];  const float* b1 = (const float*)d_in[4];
    const float* W2 = (const float*)d_in[5];  const float* b2 = (const float*)d_in[6];
    const float* W3 = (const float*)d_in[7];  const float* b3 = (const float*)d_in[8];
    const float* W4 = (const float*)d_in[9];  const float* b4 = (const float*)d_in[10];
    const float* Wout = (const float*)d_in[11]; const float* bout = (const float*)d_in[12];

    int N = in_sizes[0] / 128;
    int E = in_sizes[1] / 2;
    int G = out_size / 129;  // out[G,1] + pooled[G,128]

    const int* src = edge;
    const int* dst = edge + E;

    float* out_p    = (float*)d_out;
    float* pooled_p = out_p + G;

    __half *tptr = nullptr, *aptr = nullptr;
    cudaGetSymbolAddress((void**)&tptr, g_t16);
    cudaGetSymbolAddress((void**)&aptr, g_agg16);

    int nsb      = (N + SCAN_BLK - 1) / SCAN_BLK;   // <= 98
    int gblocks  = (N + 127) / 128;
    int agblocks = (N + 7) / 8;
    int e4blocks = ((E + 3) / 4 + 255) / 256;

    // ---- prep (g_deg is zero at rest; scan_part re-zeroes it) ----
    count_deg_kernel<<<e4blocks, 256>>>(dst, E);                    // 0
    scan_part_kernel<<<nsb, 256>>>(N);                              // 1  (dis + zero deg)
    scan_fixup_kernel<<<(N + 256) / 256, 256>>>(N, E, nsb);         // 2
    permute_kernel<<<e4blocks, 256>>>(src, dst, E);                 // 3  (profiled slot)

    gemm_tc_kernel<128, float><<<gblocks, 256>>>(x, W1, tptr, N);   // 4
    gather_kernel<<<agblocks, 256>>>(b1, N);
    // layers 2..4 (fp16 activations in, fp16 t' out)
    gemm_tc_kernel<64, __half><<<gblocks, 256>>>(aptr, W2, tptr, N);
    gather_kernel<<<agblocks, 256>>>(b2, N);

    gemm_tc_kernel<64, __half><<<gblocks, 256>>>(aptr, W3, tptr, N);
    gather_kernel<<<agblocks, 256>>>(b3, N);

    gemm_tc_kernel<64, __half><<<gblocks, 256>>>(aptr, W4, tptr, N);
    gather_kernel<<<agblocks, 256>>>(b4, N);

    // pooling (+ fused output linear)
    pool_out_kernel<<<G, 64>>>(batch, Wout, bout, out_p, pooled_p, N);
}

// round 17
// speedup vs baseline: 1.0010x; 1.0010x over previous
#include <cuda_runtime.h>
#include <cuda_fp16.h>

#define MAXN 100000
#define MAXE 1600000
#define HID 64
#define SCAN_BLK 1024
#define MAX_SCAN_BLOCKS 256

// ---- scratch (device globals; no allocation allowed) ----
// g_t16 holds t'[i] = (h @ W)[i] * dis[i]  (fp16)
__device__ __align__(256) __half g_t16[MAXN * HID];
__device__ __align__(256) __half g_agg16[MAXN * HID]; // relu(conv) output (fp16)
__device__ __align__(256) float g_dis[MAXN];          // deg^{-1/2}
__device__ __align__(256) int   g_deg[MAXN];          // zero at rest (self-restoring)
__device__ __align__(256) int   g_rowptr[MAXN + 1];
__device__ __align__(256) int   g_cursor[MAXN];
__device__ __align__(256) int   g_blocksum[MAX_SCAN_BLOCKS];
__device__ int g_arrive;   // zero at rest (self-restoring spin barrier)
__device__ int g_depart;
__device__ __align__(256) int   g_srcs[MAXE + 4];     // CSR: src node per slot

// ---------------- prep ----------------
// 4 edges per thread via int4.
__global__ void count_deg_kernel(const int* __restrict__ dst, int E) {
    int e = (blockIdx.x * blockDim.x + threadIdx.x) * 4;
    if (e + 4 <= E) {
        int4 d = *(const int4*)(dst + e);
        atomicAdd(&g_deg[d.x], 1);
        atomicAdd(&g_deg[d.y], 1);
        atomicAdd(&g_deg[d.z], 1);
        atomicAdd(&g_deg[d.w], 1);
    } else {
        for (; e < E; e++) atomicAdd(&g_deg[dst[e]], 1);
    }
}

// Single-kernel exclusive scan of g_deg -> g_rowptr (+dis, +deg-zeroing,
// +cursor-zeroing). Uses a self-resetting grid spin barrier: nsb <= 98 blocks
// all fit in one wave (148 SMs) so spinning is deadlock-free. Last departing
// block resets the counters so the CUDA-graph replay starts clean.
__global__ void scan_all_kernel(int n, int E, int nsb) {
    __shared__ int sm[256];
    int tid = threadIdx.x;
    int b = blockIdx.x;
    int base = b * SCAN_BLK + tid * 4;
    int v[4];
#pragma unroll
    for (int j = 0; j < 4; j++) {
        v[j] = (base + j < n) ? g_deg[base + j] : 0;
        if (base + j < n) {
            g_dis[base + j] = rsqrtf((float)(v[j] + 1));
            g_deg[base + j] = 0;
        }
    }
    int tsum = v[0] + v[1] + v[2] + v[3];
    sm[tid] = tsum;
    __syncthreads();
#pragma unroll
    for (int off = 1; off < 256; off <<= 1) {
        int t2 = (tid >= off) ? sm[tid - off] : 0;
        __syncthreads();
        sm[tid] += t2;
        __syncthreads();
    }
    int local_ex = sm[tid] - tsum;  // exclusive within block

    if (tid == 0) {
        g_blocksum[b] = sm[255];
        __threadfence();
        atomicAdd(&g_arrive, 1);
        while (atomicAdd(&g_arrive, 0) < nsb) { }
    }
    __syncthreads();

    // block offset = sum of blocksums before b (thread-redundant, <=98 reads)
    int off = 0;
    for (int i = 0; i < b; i++) off += __ldcg(&g_blocksum[i]);

    int run = off + local_ex;
#pragma unroll
    for (int j = 0; j < 4; j++) {
        if (base + j < n) {
            g_rowptr[base + j] = run;
            g_cursor[base + j] = 0;
        }
        run += v[j];
    }
    if (b == 0 && tid == 0) g_rowptr[n] = E;

    __syncthreads();
    if (tid == 0) {
        int d = atomicAdd(&g_depart, 1);
        if (d == nsb - 1) { g_arrive = 0; g_depart = 0; }  // reset for replay
    }
}

// ---------------- tf32 MMA helpers ----------------
__device__ __forceinline__ unsigned int f2tf32(float f) {
    unsigned int u;
    asm("cvt.rna.tf32.f32 %0, %1;" : "=r"(u) : "f"(f));
    return u;
}

__device__ __forceinline__ float ld_elem(const float* p)  { return *p; }
__device__ __forceinline__ float ld_elem(const __half* p) { return __half2float(*p); }

__device__ __forceinline__ void mma_tf32(float* c,
                                         unsigned int a0, unsigned int a1,
                                         unsigned int a2, unsigned int a3,
                                         unsigned int b0, unsigned int b1) {
    asm volatile(
        "mma.sync.aligned.m16n8k8.row.col.f32.tf32.tf32.f32 "
        "{%0,%1,%2,%3}, {%4,%5,%6,%7}, {%8,%9}, {%0,%1,%2,%3};"
        : "+f"(c[0]), "+f"(c[1]), "+f"(c[2]), "+f"(c[3])
        : "r"(a0), "r"(a1), "r"(a2), "r"(a3), "r"(b0), "r"(b1));
}

// GEMM body: tile = 128 nodes x 64 cols; 8 warps; warp = 16 nodes.
// A direct from gmem; W in smem stride 72 (==8 mod 32, conflict-free).
// Epilogue scales row by dis[row], stores fp16.
template <int K, typename T>
__device__ __forceinline__ void gemm_body(const T* __restrict__ in,
                                          const float* __restrict__ W,
                                          __half* __restrict__ out, int n,
                                          int blk, unsigned int* ws) {
    constexpr int SW = 72;
    const int tid = threadIdx.x;
    const int base = blk * 128;

    {
        const float4* W4 = (const float4*)W;
        for (int i = tid; i < K * 16; i += 256) {
            int row = i >> 4, c4 = i & 15;
            float4 v = W4[i];
            uint4 u = make_uint4(f2tf32(v.x), f2tf32(v.y), f2tf32(v.z), f2tf32(v.w));
            *(uint4*)(ws + row * SW + c4 * 4) = u;
        }
    }
    __syncthreads();

    const int wid  = tid >> 5;
    const int lane = tid & 31;
    const int g    = lane >> 2;
    const int tg   = lane & 3;

    int r0 = base + wid * 16 + g;
    int r1 = r0 + 8;
    bool p0 = r0 < n, p1 = r1 < n;
    const T* x0 = in + (size_t)(p0 ? r0 : 0) * K + tg;
    const T* x1 = in + (size_t)(p1 ? r1 : 0) * K + tg;

    float c[8][4];
#pragma unroll
    for (int nt = 0; nt < 8; nt++)
#pragma unroll
        for (int j = 0; j < 4; j++) c[nt][j] = 0.f;

#pragma unroll
    for (int ks = 0; ks < K / 8; ks++) {
        unsigned int a0 = f2tf32(p0 ? ld_elem(x0 + ks * 8)     : 0.f);
        unsigned int a2 = f2tf32(p0 ? ld_elem(x0 + ks * 8 + 4) : 0.f);
        unsigned int a1 = f2tf32(p1 ? ld_elem(x1 + ks * 8)     : 0.f);
        unsigned int a3 = f2tf32(p1 ? ld_elem(x1 + ks * 8 + 4) : 0.f);
        const unsigned int* bp = ws + (ks * 8 + tg) * SW + g;
#pragma unroll
        for (int nt = 0; nt < 8; nt++) {
            unsigned int b0 = bp[nt * 8];
            unsigned int b1 = bp[nt * 8 + 4 * SW];
            mma_tf32(c[nt], a0, a1, a2, a3, b0, b1);
        }
    }

    float d0 = p0 ? g_dis[r0] : 0.f;
    float d1 = p1 ? g_dis[r1] : 0.f;
#pragma unroll
    for (int nt = 0; nt < 8; nt++) {
        int col = nt * 8 + tg * 2;
        if (p0) {
            __half2 h = __floats2half2_rn(c[nt][0] * d0, c[nt][1] * d0);
            *(__half2*)(out + (size_t)r0 * 64 + col) = h;
        }
        if (p1) {
            __half2 h = __floats2half2_rn(c[nt][2] * d1, c[nt][3] * d1);
            *(__half2*)(out + (size_t)r1 * 64 + col) = h;
        }
    }
}

// Merged launch: blocks [0, gblocks) run the layer-1 GEMM; blocks
// [gblocks, gblocks+pblocks) run the CSR permute. Independent work,
// one launch -> they overlap across SMs without stream forking.
__global__ __launch_bounds__(256) void permute_gemm_kernel(
        const int* __restrict__ src, const int* __restrict__ dst, int E,
        const float* __restrict__ x, const float* __restrict__ W1,
        __half* __restrict__ out, int n, int gblocks) {
    __shared__ unsigned int ws[128 * 72];
    if ((int)blockIdx.x < gblocks) {
        gemm_body<128, float>(x, W1, out, n, blockIdx.x, ws);
        return;
    }
    int e = ((blockIdx.x - gblocks) * blockDim.x + threadIdx.x) * 4;
    if (e + 4 <= E) {
        int4 s = *(const int4*)(src + e);
        int4 d = *(const int4*)(dst + e);
        int p0 = atomicAdd(&g_cursor[d.x], 1);
        g_srcs[g_rowptr[d.x] + p0] = s.x;
        int p1 = atomicAdd(&g_cursor[d.y], 1);
        g_srcs[g_rowptr[d.y] + p1] = s.y;
        int p2 = atomicAdd(&g_cursor[d.z], 1);
        g_srcs[g_rowptr[d.z] + p2] = s.z;
        int p3 = atomicAdd(&g_cursor[d.w], 1);
        g_srcs[g_rowptr[d.w] + p3] = s.w;
    } else {
        for (; e < E; e++) {
            int d = dst[e];
            int pos = atomicAdd(&g_cursor[d], 1);
            g_srcs[g_rowptr[d] + pos] = src[e];
        }
    }
}

// Standalone GEMM for layers 2..4 (fp16 in).
template <int K, typename T>
__global__ __launch_bounds__(256) void gemm_tc_kernel(const T* __restrict__ in,
                                                      const float* __restrict__ W,
                                                      __half* __restrict__ out, int n) {
    __shared__ unsigned int ws[K * 72];
    gemm_body<K, T>(in, W, out, n, blockIdx.x, ws);
}

// ---------------- CSR gather (warp per node, 4B edges, fp16 out) -----------
// agg[d] = relu( dis[d] * (sum_e t'[src_e] + t'[d]) + b )
__global__ __launch_bounds__(256) void gather_kernel(const float* __restrict__ b,
                                                     int n) {
    int node = blockIdx.x * 8 + (threadIdx.x >> 5);  // 8 warps/block
    int l = threadIdx.x & 31;
    if (node >= n) return;

    const __half2* t2 = (const __half2*)g_t16;

    float2 acc = __half22float2(t2[node * 32 + l]);  // self-loop term t'[d]
    int e  = g_rowptr[node];
    int e1 = g_rowptr[node + 1];
    for (; e + 4 <= e1; e += 4) {
        int s0 = g_srcs[e];
        int s1 = g_srcs[e + 1];
        int s2 = g_srcs[e + 2];
        int s3 = g_srcs[e + 3];
        float2 f0 = __half22float2(t2[s0 * 32 + l]);
        float2 f1 = __half22float2(t2[s1 * 32 + l]);
        float2 f2 = __half22float2(t2[s2 * 32 + l]);
        float2 f3 = __half22float2(t2[s3 * 32 + l]);
        acc.x += f0.x + f1.x + f2.x + f3.x;
        acc.y += f0.y + f1.y + f2.y + f3.y;
    }
    for (; e < e1; e++) {
        float2 f0 = __half22float2(t2[g_srcs[e] * 32 + l]);
        acc.x += f0.x;
        acc.y += f0.y;
    }

    float dd = g_dis[node];
    float2 bb = ((const float2*)b)[l];
    float rx = fmaxf(fmaf(dd, acc.x, bb.x), 0.f);
    float ry = fmaxf(fmaf(dd, acc.y, bb.y), 0.f);
    ((__half2*)g_agg16)[node * 32 + l] = __floats2half2_rn(rx, ry);
}

// ---------------- pooling + output linear (MLP-4 node loop) ----------------
__global__ void pool_out_kernel(const int* __restrict__ batch,
                                const float* __restrict__ Wout,
                                const float* __restrict__ bout,
                                float* __restrict__ out,
                                float* __restrict__ pooled, int n) {
    int g = blockIdx.x;
    int c = threadIdx.x;  // 64 threads

    int a = 0, b = n;
    while (a < b) { int m = (a + b) >> 1; if (batch[m] < g) a = m + 1; else b = m; }
    int start = a;
    b = n;
    while (a < b) { int m = (a + b) >> 1; if (batch[m] <= g) a = m + 1; else b = m; }
    int end = a;

    float sum = 0.f, mx = 0.f;
    int i = start;
    for (; i + 4 <= end; i += 4) {
        float v0 = __half2float(g_agg16[(size_t)i * 64 + c]);
        float v1 = __half2float(g_agg16[(size_t)(i + 1) * 64 + c]);
        float v2 = __half2float(g_agg16[(size_t)(i + 2) * 64 + c]);
        float v3 = __half2float(g_agg16[(size_t)(i + 3) * 64 + c]);
        sum += (v0 + v1) + (v2 + v3);
        mx = fmaxf(fmaxf(mx, fmaxf(v0, v1)), fmaxf(v2, v3));
    }
    for (; i < end; i++) {
        float v = __half2float(g_agg16[(size_t)i * 64 + c]);
        sum += v;
        mx = fmaxf(mx, v);
    }
    int cnt = end - start;
    float mean = (cnt > 0) ? sum / (float)cnt : 0.f;

    pooled[(size_t)g * 128 + c] = mean;
    pooled[(size_t)g * 128 + 64 + c] = mx;

    float partial = mean * Wout[c] + mx * Wout[64 + c];
#pragma unroll
    for (int o = 16; o > 0; o >>= 1)
        partial += __shfl_down_sync(0xffffffffu, partial, o);
    __shared__ float ws[2];
    if ((threadIdx.x & 31) == 0) ws[threadIdx.x >> 5] = partial;
    __syncthreads();
    if (threadIdx.x == 0) out[g] = ws[0] + ws[1] + bout[0];
}

// ---------------- host ----------------
extern "C" void kernel_launch(void* const* d_in, const int* in_sizes, int n_in,
                              void* d_out, int out_size) {
    const float* x     = (const float*)d_in[0];
    const int*   edge  = (const int*)d_in[1];     // int64 inputs arrive as int32
    const int*   batch = (const int*)d_in[2];
    const float* W1 = (const float*)d_in[3];  const float* b1 = (const float*)d_in[4];
    const float* W2 = (const float*)d_in[5];  const float* b2 = (const float*)d_in[6];
    const float* W3 = (const float*)d_in[7];  const float* b3 = (const float*)d_in[8];
    const float* W4 = (const float*)d_in[9];  const float* b4 = (const float*)d_in[10];
    const float* Wout = (const float*)d_in[11]; const float* bout = (const float*)d_in[12];

    int N = in_sizes[0] / 128;
    int E = in_sizes[1] / 2;
    int G = out_size / 129;  // out[G,1] + pooled[G,128]

    const int* src = edge;
    const int* dst = edge + E;

    float* out_p    = (float*)d_out;
    float* pooled_p = out_p + G;

    __half *tptr = nullptr, *aptr = nullptr;
    cudaGetSymbolAddress((void**)&tptr, g_t16);
    cudaGetSymbolAddress((void**)&aptr, g_agg16);

    int nsb      = (N + SCAN_BLK - 1) / SCAN_BLK;   // <= 98 (fits one wave)
    int gblocks  = (N + 127) / 128;
    int agblocks = (N + 7) / 8;
    int e4blocks = ((E + 3) / 4 + 255) / 256;

    // ---- prep (g_deg zero at rest; scan_all re-zeroes it + spin barrier) ----
    count_deg_kernel<<<e4blocks, 256>>>(dst, E);                    // launch 1
    scan_all_kernel<<<nsb, 256>>>(N, E, nsb);                       // launch 2
    // layer-1 GEMM merged with permute: independent work, one launch
    permute_gemm_kernel<<<gblocks + e4blocks, 256>>>(src, dst, E,
                                                     x, W1, tptr, N, gblocks); // 3
    gather_kernel<<<agblocks, 256>>>(b1, N);                        // launch 4 (profiled)
    // layers 2..4 (fp16 activations in, fp16 t' out)
    gemm_tc_kernel<64, __half><<<gblocks, 256>>>(aptr, W2, tptr, N);
    gather_kernel<<<agblocks, 256>>>(b2, N);

    gemm_tc_kernel<64, __half><<<gblocks, 256>>>(aptr, W3, tptr, N);
    gather_kernel<<<agblocks, 256>>>(b3, N);

    gemm_tc_kernel<64, __half><<<gblocks, 256>>>(aptr, W4, tptr, N);
    gather_kernel<<<agblocks, 256>>>(b4, N);

    // pooling (+ fused output linear)
    pool_out_kernel<<<G, 64>>>(batch, Wout, bout, out_p, pooled_p, N);
}